// round 3
// baseline (speedup 1.0000x reference)
#include <cuda_runtime.h>

#define NB 4
#define C  128
#define Q  4096   // HS*WS = HR*WR
#define S  64
#define WS_ 64
#define HS_ 64

// Scratch: transposed features, (n, q, c) layout.
__device__ float g_fr_t[(size_t)NB * Q * C];
__device__ float g_fs_t[(size_t)NB * Q * C];

// Precomputed per-sample records: 4 corner offsets (already *C) + 4 weights.
struct __align__(32) SampleRec {
    int4   qoff;   // corner row offsets, units of floats (q * C)
    float4 w;      // bilinear weights with in-bounds folded in
};
__device__ SampleRec g_rec[(size_t)NB * Q * S];
__device__ float     g_cmmv[(size_t)NB * Q * S];   // corr_mask * input mask

// ---------------------------------------------------------------------------
// Transpose (n, C, Q) -> (n, Q, C) for both fr and fs.
// grid (Q/32, C/32, 2*NB), block (32, 8)
__global__ void transpose_cq(const float* __restrict__ fr,
                             const float* __restrict__ fs) {
    __shared__ float tile[32][33];
    const int which = blockIdx.z >> 2;
    const int n     = blockIdx.z & 3;
    const float* src = which ? fs : fr;
    float* dst       = which ? g_fs_t : g_fr_t;

    const int q0 = blockIdx.x * 32;
    const int c0 = blockIdx.y * 32;

    const float* sp = src + ((size_t)n * C + c0) * Q + q0;
#pragma unroll
    for (int k = 0; k < 4; ++k)
        tile[threadIdx.y + k * 8][threadIdx.x] =
            sp[(size_t)(threadIdx.y + k * 8) * Q + threadIdx.x];
    __syncthreads();

    float* dp = dst + ((size_t)n * Q + q0) * C + c0;
#pragma unroll
    for (int k = 0; k < 4; ++k)
        dp[(size_t)(threadIdx.y + k * 8) * C + threadIdx.x] =
            tile[threadIdx.x][threadIdx.y + k * 8];
}

// ---------------------------------------------------------------------------
// Precompute per-sample corner offsets / weights / combined mask.
// grid (Q/256, S, NB), block 256. Thread = p (coalesced input reads).
__global__ __launch_bounds__(256)
void precompute_samples(const float* __restrict__ grids,
                        const float* __restrict__ mask) {
    const int p = blockIdx.x * 256 + threadIdx.x;
    const int s = blockIdx.y;
    const int n = blockIdx.z;

    const float gx = grids[(((size_t)n * S + s) * 2 + 0) * Q + p];
    const float gy = grids[(((size_t)n * S + s) * 2 + 1) * Q + p];
    const float mv = mask[((size_t)n * S + s) * Q + p];

    const float ix = gx - 0.5f;
    const float iy = gy - 0.5f;
    const float x0 = floorf(ix);
    const float y0 = floorf(iy);
    const float wx1 = ix - x0;
    const float wy1 = iy - y0;
    const int x0i = (int)x0;
    const int y0i = (int)y0;

    SampleRec r;
    float msum = 0.0f;
    int   qo[4];
    float wv[4];
#pragma unroll
    for (int k = 0; k < 4; ++k) {
        const int dx = k & 1;
        const int dy = k >> 1;
        const int xi = x0i + dx;
        const int yi = y0i + dy;
        const bool inb = (xi >= 0) && (xi < WS_) && (yi >= 0) && (yi < HS_);
        const float wk = (dx ? wx1 : 1.0f - wx1) *
                         (dy ? wy1 : 1.0f - wy1) * (inb ? 1.0f : 0.0f);
        wv[k] = wk;
        msum += wk;
        const int xc = min(max(xi, 0), WS_ - 1);
        const int yc = min(max(yi, 0), HS_ - 1);
        qo[k] = (yc * WS_ + xc) * C;
    }
    r.qoff = make_int4(qo[0], qo[1], qo[2], qo[3]);
    r.w    = make_float4(wv[0], wv[1], wv[2], wv[3]);

    const float cm = (msum < 0.9999f) ? 0.0f : 1.0f;

    const size_t sidx = ((size_t)n * Q + p) * S + s;
    g_rec[sidx]  = r;
    g_cmmv[sidx] = cm * mv;
}

// ---------------------------------------------------------------------------
// Hot kernel: one warp per (n, p). 64 samples; gather 4 corner rows
// (float4 per lane), weighted blend + dot with fr row; smem transpose-
// reduce every 32 samples.
// grid (Q/8, NB), block 256 (8 warps)
__global__ __launch_bounds__(256, 3)
void corr_sample_kernel(float* __restrict__ out) {
    const int lane = threadIdx.x & 31;
    const int warp = threadIdx.x >> 5;
    const int n    = blockIdx.y;
    const int p    = blockIdx.x * 8 + warp;

    const float4 fr4 = *(const float4*)(g_fr_t + ((size_t)n * Q + p) * C + lane * 4);
    const float* fsl = g_fs_t + (size_t)n * Q * C + lane * 4;

    const size_t base = ((size_t)n * Q + p) * S;
    const SampleRec* rec = g_rec + base;

    __shared__ float red[8][32][33];
    __shared__ float s_out[S][8];
    __shared__ float s_cm[S][8];

#pragma unroll
    for (int half = 0; half < 2; ++half) {
#pragma unroll 2
        for (int j = 0; j < 32; ++j) {
            const int s = half * 32 + j;
            const int4   qo = __ldg(&rec[s].qoff);
            const float4 w  = __ldg(&rec[s].w);

            const float4 f0 = __ldg((const float4*)(fsl + qo.x));
            const float4 f1 = __ldg((const float4*)(fsl + qo.y));
            const float4 f2 = __ldg((const float4*)(fsl + qo.z));
            const float4 f3 = __ldg((const float4*)(fsl + qo.w));

            float vx = w.x * f0.x + w.y * f1.x + w.z * f2.x + w.w * f3.x;
            float vy = w.x * f0.y + w.y * f1.y + w.z * f2.y + w.w * f3.y;
            float vz = w.x * f0.z + w.y * f1.z + w.z * f2.z + w.w * f3.z;
            float vw = w.x * f0.w + w.y * f1.w + w.z * f2.w + w.w * f3.w;

            red[warp][j][lane] = fr4.x * vx + fr4.y * vy + fr4.z * vz + fr4.w * vw;
        }
        __syncwarp();

        // Lane l reduces sample (half*32 + l).
        float tot = 0.0f;
#pragma unroll
        for (int k = 0; k < 32; ++k)
            tot += red[warp][lane][k];

        const float cmmv = __ldg(&g_cmmv[base + half * 32 + lane]);
        s_out[half * 32 + lane][warp] = tot * cmmv;
        s_cm[half * 32 + lane][warp]  = cmmv;
        __syncwarp();
    }

    __syncthreads();

    // Coalesced writeback: out (n,s,p) then corr_mask (n,s,p)
    float* outp = out + (size_t)n * S * Q + blockIdx.x * 8;
    float* cmp  = outp + (size_t)NB * S * Q;
    for (int t = threadIdx.x; t < S * 8; t += 256) {
        const int s = t >> 3;
        const int j = t & 7;
        outp[(size_t)s * Q + j] = s_out[s][j];
        cmp[(size_t)s * Q + j]  = s_cm[s][j];
    }
}

extern "C" void kernel_launch(void* const* d_in, const int* in_sizes, int n_in,
                              void* d_out, int out_size) {
    const float* fr    = (const float*)d_in[0];
    const float* fs    = (const float*)d_in[1];
    const float* grids = (const float*)d_in[2];
    const float* mask  = (const float*)d_in[3];
    float* out = (float*)d_out;

    transpose_cq<<<dim3(Q / 32, C / 32, 2 * NB), dim3(32, 8)>>>(fr, fs);
    precompute_samples<<<dim3(Q / 256, S, NB), 256>>>(grids, mask);
    corr_sample_kernel<<<dim3(Q / 8, NB), 256>>>(out);
}

// round 4
// speedup vs baseline: 1.7842x; 1.7842x over previous
#include <cuda_runtime.h>
#include <cuda_fp16.h>

#define NB 4
#define C  128
#define Q  4096   // HS*WS = HR*WR
#define S  64
#define WS_ 64
#define HS_ 64

// Scratch: transposed features, (n, q, c) layout. fr fp32, fs fp16.
__device__ float  g_fr_t[(size_t)NB * Q * C];
__device__ __half g_fs_t[(size_t)NB * Q * C];

// Precomputed per-sample records: 4 corner row offsets (element units, q*C)
// + 4 bilinear weights with in-bounds folded in.
struct __align__(32) SampleRec {
    int4   qoff;
    float4 w;
};
__device__ SampleRec g_rec[(size_t)NB * Q * S];
__device__ float     g_cmmv[(size_t)NB * Q * S];   // corr_mask * input mask

// ---------------------------------------------------------------------------
// Fused prelude: one launch does fr transpose (fp32), fs transpose (fp16),
// and per-sample record precompute, dispatched by blockIdx.x range.
//   [0,      2048)  fr transpose   (128 qtiles x 4 ctiles x 4 n)
//   [2048,   4096)  fs transpose
//   [4096,   8192)  precompute     (16 ptiles x 64 s x 4 n)
__global__ __launch_bounds__(256)
void prelude_kernel(const float* __restrict__ fr,
                    const float* __restrict__ fs,
                    const float* __restrict__ grids,
                    const float* __restrict__ mask) {
    const int bid = blockIdx.x;

    if (bid < 4096) {
        // ---- transpose (n, C, Q) -> (n, Q, C) ----
        __shared__ float tile[32][33];
        const bool is_fs = bid >= 2048;
        const int  b     = bid & 2047;
        const int  n     = b >> 9;           // 512 blocks per batch
        const int  r     = b & 511;          // 128 qtiles x 4 ctiles
        const int  q0    = (r >> 2) * 32;
        const int  c0    = (r & 3) * 32;

        const int tx = threadIdx.x & 31;
        const int ty = threadIdx.x >> 5;

        const float* src = is_fs ? fs : fr;
        const float* sp  = src + ((size_t)n * C + c0) * Q + q0;
#pragma unroll
        for (int k = 0; k < 4; ++k)
            tile[ty + k * 8][tx] = sp[(size_t)(ty + k * 8) * Q + tx];
        __syncthreads();

        if (is_fs) {
            __half* dp = g_fs_t + ((size_t)n * Q + q0) * C + c0;
#pragma unroll
            for (int k = 0; k < 4; ++k)
                dp[(size_t)(ty + k * 8) * C + tx] =
                    __float2half(tile[tx][ty + k * 8]);
        } else {
            float* dp = g_fr_t + ((size_t)n * Q + q0) * C + c0;
#pragma unroll
            for (int k = 0; k < 4; ++k)
                dp[(size_t)(ty + k * 8) * C + tx] = tile[tx][ty + k * 8];
        }
    } else {
        // ---- per-sample record precompute ----
        const int b = bid - 4096;
        const int n = b >> 10;               // 1024 blocks per batch
        const int r = b & 1023;              // 16 ptiles x 64 s
        const int s = r >> 4;
        const int p = (r & 15) * 256 + threadIdx.x;

        const float gx = grids[(((size_t)n * S + s) * 2 + 0) * Q + p];
        const float gy = grids[(((size_t)n * S + s) * 2 + 1) * Q + p];
        const float mv = mask[((size_t)n * S + s) * Q + p];

        const float ix = gx - 0.5f;
        const float iy = gy - 0.5f;
        const float x0 = floorf(ix);
        const float y0 = floorf(iy);
        const float wx1 = ix - x0;
        const float wy1 = iy - y0;
        const int x0i = (int)x0;
        const int y0i = (int)y0;

        SampleRec rec;
        float msum = 0.0f;
        int   qo[4];
        float wv[4];
#pragma unroll
        for (int k = 0; k < 4; ++k) {
            const int dx = k & 1;
            const int dy = k >> 1;
            const int xi = x0i + dx;
            const int yi = y0i + dy;
            const bool inb = (xi >= 0) && (xi < WS_) && (yi >= 0) && (yi < HS_);
            const float wk = (dx ? wx1 : 1.0f - wx1) *
                             (dy ? wy1 : 1.0f - wy1) * (inb ? 1.0f : 0.0f);
            wv[k] = wk;
            msum += wk;
            const int xc = min(max(xi, 0), WS_ - 1);
            const int yc = min(max(yi, 0), HS_ - 1);
            qo[k] = (yc * WS_ + xc) * C;
        }
        rec.qoff = make_int4(qo[0], qo[1], qo[2], qo[3]);
        rec.w    = make_float4(wv[0], wv[1], wv[2], wv[3]);

        const float cm = (msum < 0.9999f) ? 0.0f : 1.0f;
        const size_t sidx = ((size_t)n * Q + p) * S + s;
        g_rec[sidx]  = rec;
        g_cmmv[sidx] = cm * mv;
    }
}

// ---------------------------------------------------------------------------
// Hot kernel: one warp per (n, p). Two-stage unroll-4: stage 1 issues
// all 16 corner gathers (fp16, LDG.64 each) + 8 uniform record loads;
// stage 2 converts/blends/dots in fp32; 4 interleaved shfl reductions.
// grid (Q/8, NB), block 256 (8 warps)
__global__ __launch_bounds__(256, 3)
void corr_sample_kernel(float* __restrict__ out) {
    const int lane = threadIdx.x & 31;
    const int warp = threadIdx.x >> 5;
    const int n    = blockIdx.y;
    const int p    = blockIdx.x * 8 + warp;

    const float4 fr4 = *(const float4*)(g_fr_t + ((size_t)n * Q + p) * C + lane * 4);
    const __half* fsl = g_fs_t + (size_t)n * Q * C + lane * 4;

    const size_t base = ((size_t)n * Q + p) * S;

    // Prefetch combined masks: lane l holds s=l and s=l+32.
    const float cm_lo = __ldg(&g_cmmv[base + lane]);
    const float cm_hi = __ldg(&g_cmmv[base + 32 + lane]);

    __shared__ float s_out[S][8];
    __shared__ float s_cm[S][8];

    for (int s4 = 0; s4 < S; s4 += 4) {
        uint2  f[4][4];
        float4 w[4];

        // Stage 1: issue all loads.
#pragma unroll
        for (int j = 0; j < 4; ++j) {
            const SampleRec* rp = &g_rec[base + s4 + j];
            const int4 qo = __ldg((const int4*)&rp->qoff);
            w[j] = __ldg((const float4*)&rp->w);
            f[j][0] = __ldg((const uint2*)(fsl + qo.x));
            f[j][1] = __ldg((const uint2*)(fsl + qo.y));
            f[j][2] = __ldg((const uint2*)(fsl + qo.z));
            f[j][3] = __ldg((const uint2*)(fsl + qo.w));
        }

        // Stage 2: convert + blend + dot (fp32).
        float dacc[4];
#pragma unroll
        for (int j = 0; j < 4; ++j) {
            float vx = 0.f, vy = 0.f, vz = 0.f, vw = 0.f;
#pragma unroll
            for (int k = 0; k < 4; ++k) {
                const float wk = (k == 0) ? w[j].x : (k == 1) ? w[j].y
                               : (k == 2) ? w[j].z : w[j].w;
                const __half2* hp = (const __half2*)&f[j][k];
                const float2 lo = __half22float2(hp[0]);
                const float2 hi = __half22float2(hp[1]);
                vx += wk * lo.x;
                vy += wk * lo.y;
                vz += wk * hi.x;
                vw += wk * hi.y;
            }
            dacc[j] = fr4.x * vx + fr4.y * vy + fr4.z * vz + fr4.w * vw;
        }

        // 4 interleaved butterfly reductions.
#pragma unroll
        for (int o = 16; o; o >>= 1) {
#pragma unroll
            for (int j = 0; j < 4; ++j)
                dacc[j] += __shfl_xor_sync(0xFFFFFFFFu, dacc[j], o);
        }

        // Combined mask for these 4 samples via shfl from the holder lane.
#pragma unroll
        for (int j = 0; j < 4; ++j) {
            const int s = s4 + j;
            const float src = (s < 32) ? cm_lo : cm_hi;
            const float cmv = __shfl_sync(0xFFFFFFFFu, src, s & 31);
            if (lane == 0) {
                s_out[s][warp] = dacc[j] * cmv;
                s_cm[s][warp]  = cmv;
            }
        }
    }

    __syncthreads();

    // Coalesced writeback: out (n,s,p) then corr_mask (n,s,p)
    float* outp = out + (size_t)n * S * Q + blockIdx.x * 8;
    float* cmp  = outp + (size_t)NB * S * Q;
    for (int t = threadIdx.x; t < S * 8; t += 256) {
        const int s = t >> 3;
        const int j = t & 7;
        outp[(size_t)s * Q + j] = s_out[s][j];
        cmp[(size_t)s * Q + j]  = s_cm[s][j];
    }
}

extern "C" void kernel_launch(void* const* d_in, const int* in_sizes, int n_in,
                              void* d_out, int out_size) {
    const float* fr    = (const float*)d_in[0];
    const float* fs    = (const float*)d_in[1];
    const float* grids = (const float*)d_in[2];
    const float* mask  = (const float*)d_in[3];
    float* out = (float*)d_out;

    prelude_kernel<<<8192, 256>>>(fr, fs, grids, mask);
    corr_sample_kernel<<<dim3(Q / 8, NB), 256>>>(out);
}